// round 3
// baseline (speedup 1.0000x reference)
#include <cuda_runtime.h>
#include <math.h>
#include <stdint.h>

// Problem constants (fixed by setup_inputs)
#define N_NODES 32768
#define NB      64
#define LSEQ    512
#define DIM     256
#define HID     512
#define GI3     1536   // 3*HID
#define EDGES   524288
#define NBLK_GRU 128

// ---------------- f32x2 packed math (sm_103a) ----------------
#define FMA2(d, a, b, c) \
    asm("fma.rn.f32x2 %0, %1, %2, %3;" : "=l"(d) : "l"(a), "l"(b), "l"(c))
#define SPLAT2(d, s) \
    asm("mov.b64 %0, {%1, %2};" : "=l"(d) : "f"(s), "f"(s))

// ---------------- scratch (static device globals; no allocation) ----------------
__device__ float g_h0 [(size_t)N_NODES * DIM];
__device__ float g_t  [(size_t)N_NODES * HID];
__device__ float g_h1 [(size_t)N_NODES * HID];
__device__ float g_h2 [(size_t)N_NODES * HID];
__device__ float g_gi [(size_t)N_NODES * GI3];
__device__ int   g_deg [N_NODES];
__device__ float g_dinv[N_NODES];
__device__ int   g_off [N_NODES + 1];
__device__ int   g_cursor[N_NODES];
__device__ int   g_csrc[EDGES];
__device__ float g_ccoef[EDGES];
__device__ float g_hbuf[2][NB * HID];
__device__ float g_hsum[NB * HID];
__device__ int   g_bar;

// ---------------- degree / CSR build ----------------
__global__ void k_count(const int* __restrict__ dst, int* __restrict__ deg, int E) {
    int i = blockIdx.x * 256 + threadIdx.x;
    if (i < E) atomicAdd(&deg[dst[i]], 1);
}

__global__ void k_dinv(const int* __restrict__ deg, float* __restrict__ dinv) {
    int i = blockIdx.x * 256 + threadIdx.x;
    if (i < N_NODES) dinv[i] = rsqrtf((float)(deg[i] + 1));  // +1 self loop
}

__global__ void __launch_bounds__(1024) k_scan(const int* __restrict__ deg,
                                               int* __restrict__ off,
                                               int* __restrict__ cursor) {
    __shared__ int ssum[1024];
    int tid = threadIdx.x;
    int base = tid * 32;
    int loc[32];
    int s = 0;
#pragma unroll
    for (int i = 0; i < 32; i++) { loc[i] = s; s += deg[base + i]; }
    ssum[tid] = s;
    __syncthreads();
    for (int ofs = 1; ofs < 1024; ofs <<= 1) {
        int v = (tid >= ofs) ? ssum[tid - ofs] : 0;
        __syncthreads();
        ssum[tid] += v;
        __syncthreads();
    }
    int pre = (tid == 0) ? 0 : ssum[tid - 1];
#pragma unroll
    for (int i = 0; i < 32; i++) { off[base + i] = pre + loc[i]; cursor[base + i] = 0; }
    if (tid == 1023) off[N_NODES] = ssum[1023];
}

__global__ void k_fill(const int* __restrict__ src, const int* __restrict__ dst,
                       const float* __restrict__ dinv, const int* __restrict__ off,
                       int* __restrict__ cursor, int* __restrict__ csrc,
                       float* __restrict__ ccoef, int E) {
    int e = blockIdx.x * 256 + threadIdx.x;
    if (e >= E) return;
    int s = src[e], d = dst[e];
    int p = atomicAdd(&cursor[d], 1);
    int slot = off[d] + p;
    csrc[slot] = s;
    ccoef[slot] = dinv[s] * dinv[d];
}

__global__ void k_embed(const int* __restrict__ x, const float* __restrict__ emb,
                        float* __restrict__ h0) {
    int n = blockIdx.x;
    int d = threadIdx.x;          // 256 threads
    h0[(size_t)n * DIM + d] = emb[(size_t)x[n] * DIM + d];
}

// ---------------- CSR gather: out = relu( sum_in t[src]*coef + t[n]*dinv^2 + bias )
__global__ void __launch_bounds__(256) k_gather(
    const float* __restrict__ t, const int* __restrict__ csrc,
    const float* __restrict__ ccoef, const int* __restrict__ off,
    const float* __restrict__ dinv, const float* __restrict__ bias,
    float* __restrict__ out) {
    int w = threadIdx.x >> 5, lane = threadIdx.x & 31;
    int n = blockIdx.x * 2 + (w >> 2);
    int chunk = w & 3;
    int c4 = chunk * 32 + lane;   // float4 column index 0..127
    float di = dinv[n];
    float sc = di * di;
    float4 v = ((const float4*)(t + (size_t)n * HID))[c4];
    float4 acc = {v.x * sc, v.y * sc, v.z * sc, v.w * sc};
    int j0 = off[n], j1 = off[n + 1];
#pragma unroll 2
    for (int j = j0; j < j1; j++) {
        int s = __ldg(&csrc[j]);
        float cf = __ldg(&ccoef[j]);
        float4 u = ((const float4*)(t + (size_t)s * HID))[c4];
        acc.x += u.x * cf; acc.y += u.y * cf; acc.z += u.z * cf; acc.w += u.w * cf;
    }
    float4 bb = ((const float4*)bias)[c4];
    float4 o = {fmaxf(acc.x + bb.x, 0.f), fmaxf(acc.y + bb.y, 0.f),
                fmaxf(acc.z + bb.z, 0.f), fmaxf(acc.w + bb.w, 0.f)};
    ((float4*)(out + (size_t)n * HID))[c4] = o;
}

// ---------------- tiled SGEMM with f32x2 inner product ----------------
// BM=64, BN=64, BK=16, 256 threads, 4x4 per thread.
template<bool TRANSB, bool ADD_BIAS>
__global__ void __launch_bounds__(256) sgemm_kernel(
    const float* __restrict__ A, const float* __restrict__ B,
    const float* __restrict__ bias, float* __restrict__ C,
    int M, int N, int K) {
    __shared__ float As[16][64];
    __shared__ float Bs[16][64];
    int tid = threadIdx.x;
    int tx = tid & 15, ty = tid >> 4;
    int row0 = blockIdx.y * 64;
    int col0 = blockIdx.x * 64;
    unsigned long long acc[4][2];
#pragma unroll
    for (int i = 0; i < 4; i++) { acc[i][0] = 0ull; acc[i][1] = 0ull; }
    int la_m = tid >> 2;
    int la_k = (tid & 3) << 2;
    for (int kk = 0; kk < K; kk += 16) {
        {
            float4 v = *(const float4*)(A + (size_t)(row0 + la_m) * K + kk + la_k);
            As[la_k + 0][la_m] = v.x; As[la_k + 1][la_m] = v.y;
            As[la_k + 2][la_m] = v.z; As[la_k + 3][la_m] = v.w;
        }
        if (TRANSB) {
            float4 v = *(const float4*)(B + (size_t)(col0 + la_m) * K + kk + la_k);
            Bs[la_k + 0][la_m] = v.x; Bs[la_k + 1][la_m] = v.y;
            Bs[la_k + 2][la_m] = v.z; Bs[la_k + 3][la_m] = v.w;
        } else {
            int lb_k = tid >> 4;
            int lb_n = (tid & 15) << 2;
            float4 v = *(const float4*)(B + (size_t)(kk + lb_k) * N + col0 + lb_n);
            *(float4*)&Bs[lb_k][lb_n] = v;
        }
        __syncthreads();
#pragma unroll
        for (int k = 0; k < 16; k++) {
            float4 a = *(const float4*)&As[k][ty << 2];
            ulonglong2 b2 = *(const ulonglong2*)&Bs[k][tx << 2];
            unsigned long long a0, a1, a2, a3;
            SPLAT2(a0, a.x); SPLAT2(a1, a.y); SPLAT2(a2, a.z); SPLAT2(a3, a.w);
            FMA2(acc[0][0], a0, b2.x, acc[0][0]); FMA2(acc[0][1], a0, b2.y, acc[0][1]);
            FMA2(acc[1][0], a1, b2.x, acc[1][0]); FMA2(acc[1][1], a1, b2.y, acc[1][1]);
            FMA2(acc[2][0], a2, b2.x, acc[2][0]); FMA2(acc[2][1], a2, b2.y, acc[2][1]);
            FMA2(acc[3][0], a3, b2.x, acc[3][0]); FMA2(acc[3][1], a3, b2.y, acc[3][1]);
        }
        __syncthreads();
    }
    float4 bb = {0, 0, 0, 0};
    if (ADD_BIAS) bb = *(const float4*)(bias + col0 + (tx << 2));
#pragma unroll
    for (int i = 0; i < 4; i++) {
        float2 lo = *(float2*)&acc[i][0];
        float2 hi = *(float2*)&acc[i][1];
        float4 o = {lo.x + bb.x, lo.y + bb.y, hi.x + bb.z, hi.y + bb.w};
        *(float4*)(C + (size_t)(row0 + (ty << 2) + i) * N + col0 + (tx << 2)) = o;
    }
}

// ---------------- persistent GRU ----------------
// 128 blocks x 256 threads; block bk owns h columns [bk*4, bk*4+4).
// Thread = (graph g = tid>>2, col c = tid&3): computes the 3 gate dots over
// full K=512 with f32x2 FMAs -> no cross-thread reduction. Whh slab stored
// gate-interleaved [c][k4][gate] (pad 513 float4); h rows padded to 129 float4.
#define HS_STRIDE 129
#define WS_STRIDE 513
#define GRU_SMEM ((64 * HS_STRIDE + 4 * WS_STRIDE) * 16)

__device__ __forceinline__ float sigmoidf_(float x) { return 1.0f / (1.0f + __expf(-x)); }

__global__ void __launch_bounds__(256, 1) k_gru_all(
    const float* __restrict__ gi, const float* __restrict__ Whh,
    const float* __restrict__ bhh, float* __restrict__ hsum,
    float* __restrict__ hbuf0, float* __restrict__ hbuf1, int* bar) {
    extern __shared__ float4 sm4[];
    float4* hs4 = sm4;
    float4* ws4 = sm4 + 64 * HS_STRIDE;
    int tid = threadIdx.x;
    int bk = blockIdx.x;
    int col0 = bk * 4;

    // load Whh slab once: ws4[c*WS_STRIDE + k4*4 + gate] = Whh[gate*HID+col0+c][k4]
#pragma unroll
    for (int i = 0; i < 6; i++) {
        int idx = tid + i * 256;       // 0..1535
        int r = idx >> 7;              // 0..11
        int k4 = idx & 127;
        int gate = r >> 2, c = r & 3;
        ws4[c * WS_STRIDE + k4 * 4 + gate] =
            __ldg((const float4*)Whh + (size_t)(gate * HID + col0 + c) * 128 + k4);
    }

    int g = tid >> 2, c = tid & 3;
    int col = col0 + c;
    float bh_r = bhh[col], bh_z = bhh[HID + col], bh_n = bhh[2 * HID + col];
    const ulonglong2* hrow = (const ulonglong2*)(hs4 + g * HS_STRIDE);
    const ulonglong2* wrow = (const ulonglong2*)(ws4 + c * WS_STRIDE);
    const float* girow = gi + (size_t)g * LSEQ * GI3 + col;
    float hsum_acc = 0.0f;
    __syncthreads();

    for (int t = 0; t < LSEQ; t++) {
        const float* hb = (t & 1) ? hbuf1 : hbuf0;
        float*       hn = (t & 1) ? hbuf0 : hbuf1;

        // prefetch gate inputs (read-once, streaming)
        const float* gp = girow + (size_t)t * GI3;
        float gir = __ldcs(gp);
        float giz = __ldcs(gp + HID);
        float gin = __ldcs(gp + 2 * HID);

        // stage h (bypass L1 - other SMs wrote it)
        const float4* hb4 = (const float4*)hb;
#pragma unroll
        for (int i = 0; i < 32; i++) {
            int idx = tid + i * 256;
            hs4[(idx >> 7) * HS_STRIDE + (idx & 127)] = __ldcg(hb4 + idx);
        }
        __syncthreads();

        unsigned long long ar = 0, az = 0, an = 0, ar2 = 0, az2 = 0, an2 = 0;
#pragma unroll 8
        for (int k4 = 0; k4 < 128; k4++) {
            ulonglong2 h2 = hrow[k4];
            ulonglong2 wr = wrow[k4 * 4 + 0];
            ulonglong2 wz = wrow[k4 * 4 + 1];
            ulonglong2 wn = wrow[k4 * 4 + 2];
            FMA2(ar,  h2.x, wr.x, ar);  FMA2(ar2, h2.y, wr.y, ar2);
            FMA2(az,  h2.x, wz.x, az);  FMA2(az2, h2.y, wz.y, az2);
            FMA2(an,  h2.x, wn.x, an);  FMA2(an2, h2.y, wn.y, an2);
        }
        float2 f0 = *(float2*)&ar,  f1 = *(float2*)&ar2;
        float sr = (f0.x + f0.y) + (f1.x + f1.y);
        f0 = *(float2*)&az;  f1 = *(float2*)&az2;
        float sz = (f0.x + f0.y) + (f1.x + f1.y);
        f0 = *(float2*)&an;  f1 = *(float2*)&an2;
        float sn = (f0.x + f0.y) + (f1.x + f1.y);

        float r  = sigmoidf_(gir + sr + bh_r);
        float z  = sigmoidf_(giz + sz + bh_z);
        float nn = tanhf(gin + r * (sn + bh_n));
        float hold = ((const float*)(hs4 + g * HS_STRIDE + bk))[c];
        float hnew = (1.0f - z) * nn + z * hold;
        __stcg(hn + g * HID + col, hnew);
        hsum_acc += hnew;

        // chip-wide barrier
        __threadfence();
        __syncthreads();
        if (tid == 0) {
            atomicAdd(bar, 1);
            int target = NBLK_GRU * (t + 1);
            while (*((volatile int*)bar) < target) { }
        }
        __syncthreads();
    }
    hsum[g * HID + col] = hsum_acc;
}

// ---------------- head ----------------
__global__ void __launch_bounds__(512) k_head(
    const float* __restrict__ hsum, const float* __restrict__ focal,
    const float* __restrict__ fc1w, const float* __restrict__ fc1b,
    const float* __restrict__ fc2w, const float* __restrict__ fc2b,
    float* __restrict__ out) {
    __shared__ float g[HID + 1];
    __shared__ float red[HID];
    int b = blockIdx.x, j = threadIdx.x;
    g[j] = hsum[b * HID + j] * (1.0f / (float)LSEQ);
    if (j == 0) g[HID] = focal[b];
    __syncthreads();
    float acc = fc1b[j];
    for (int k = 0; k < HID + 1; k++) acc += g[k] * fc1w[(size_t)k * HID + j];
    float a = fmaxf(acc, 0.0f);
    red[j] = a * fc2w[j];
    __syncthreads();
    for (int s = 256; s > 0; s >>= 1) {
        if (j < s) red[j] += red[j + s];
        __syncthreads();
    }
    if (j == 0) out[b] = sigmoidf_(red[0] + fc2b[0]);
}

// ---------------- launch ----------------
extern "C" void kernel_launch(void* const* d_in, const int* in_sizes, int n_in,
                              void* d_out, int out_size) {
    const int*   x     = (const int*)  d_in[0];
    const int*   edge  = (const int*)  d_in[1];
    const float* focal = (const float*)d_in[3];
    const float* emb   = (const float*)d_in[4];
    const float* W1    = (const float*)d_in[5];
    const float* b1    = (const float*)d_in[6];
    const float* W2    = (const float*)d_in[7];
    const float* b2    = (const float*)d_in[8];
    const float* Wih   = (const float*)d_in[9];
    const float* Whh   = (const float*)d_in[10];
    const float* bih   = (const float*)d_in[11];
    const float* bhh   = (const float*)d_in[12];
    const float* fc1w  = (const float*)d_in[13];
    const float* fc1b  = (const float*)d_in[14];
    const float* fc2w  = (const float*)d_in[15];
    const float* fc2b  = (const float*)d_in[16];
    int E = in_sizes[1] / 2;
    const int* src = edge;
    const int* dst = edge + E;

    float *h0, *t, *h1, *h2, *gi, *dinv, *hbuf, *hsum, *ccoef;
    int *deg, *off, *cursor, *csrc, *bar;
    cudaGetSymbolAddress((void**)&h0,    g_h0);
    cudaGetSymbolAddress((void**)&t,     g_t);
    cudaGetSymbolAddress((void**)&h1,    g_h1);
    cudaGetSymbolAddress((void**)&h2,    g_h2);
    cudaGetSymbolAddress((void**)&gi,    g_gi);
    cudaGetSymbolAddress((void**)&deg,   g_deg);
    cudaGetSymbolAddress((void**)&dinv,  g_dinv);
    cudaGetSymbolAddress((void**)&off,   g_off);
    cudaGetSymbolAddress((void**)&cursor,g_cursor);
    cudaGetSymbolAddress((void**)&csrc,  g_csrc);
    cudaGetSymbolAddress((void**)&ccoef, g_ccoef);
    cudaGetSymbolAddress((void**)&hbuf,  g_hbuf);
    cudaGetSymbolAddress((void**)&hsum,  g_hsum);
    cudaGetSymbolAddress((void**)&bar,   g_bar);

    cudaFuncSetAttribute(k_gru_all, cudaFuncAttributeMaxDynamicSharedMemorySize, GRU_SMEM);

    // CSR build (graph fixed for both layers)
    cudaMemsetAsync(deg, 0, N_NODES * sizeof(int), 0);
    k_count<<<(E + 255) / 256, 256>>>(dst, deg, E);
    k_dinv<<<N_NODES / 256, 256>>>(deg, dinv);
    k_scan<<<1, 1024>>>(deg, off, cursor);
    k_fill<<<(E + 255) / 256, 256>>>(src, dst, dinv, off, cursor, csrc, ccoef, E);

    // GCN layer 1
    k_embed<<<N_NODES, 256>>>(x, emb, h0);
    sgemm_kernel<false, false><<<dim3(HID / 64, N_NODES / 64), 256>>>(h0, W1, nullptr, t, N_NODES, HID, DIM);
    k_gather<<<N_NODES / 2, 256>>>(t, csrc, ccoef, off, dinv, b1, h1);

    // GCN layer 2
    sgemm_kernel<false, false><<<dim3(HID / 64, N_NODES / 64), 256>>>(h1, W2, nullptr, t, N_NODES, HID, HID);
    k_gather<<<N_NODES / 2, 256>>>(t, csrc, ccoef, off, dinv, b2, h2);

    // GRU input gates for all timesteps: gi = h2 @ Wih^T + bih
    sgemm_kernel<true, true><<<dim3(GI3 / 64, N_NODES / 64), 256>>>(h2, Wih, bih, gi, N_NODES, GI3, HID);

    // persistent GRU (reads gi directly in GEMM layout; no transpose pass)
    cudaMemsetAsync(hbuf, 0, NB * HID * sizeof(float), 0);   // hbuf[0] = h_0 = 0
    cudaMemsetAsync(bar, 0, sizeof(int), 0);
    k_gru_all<<<NBLK_GRU, 256, GRU_SMEM>>>(gi, Whh, bhh, hsum, hbuf, hbuf + NB * HID, bar);

    // head
    k_head<<<NB, 512>>>(hsum, focal, fc1w, fc1b, fc2w, fc2b, (float*)d_out);
}

// round 4
// speedup vs baseline: 1.3631x; 1.3631x over previous
#include <cuda_runtime.h>
#include <math.h>
#include <stdint.h>

// Problem constants (fixed by setup_inputs)
#define N_NODES 32768
#define NB      64
#define LSEQ    512
#define DIM     256
#define HID     512
#define GI3     1536   // 3*HID
#define EDGES   524288
#define NBLK_GRU 128

// ---------------- f32x2 packed math (sm_103a) ----------------
#define FMA2(d, a, b, c) \
    asm("fma.rn.f32x2 %0, %1, %2, %3;" : "=l"(d) : "l"(a), "l"(b), "l"(c))

// ---------------- scratch (static device globals; no allocation) ----------------
__device__ float g_h0 [(size_t)N_NODES * DIM];
__device__ float g_t  [(size_t)N_NODES * HID];
__device__ float g_h1 [(size_t)N_NODES * HID];
__device__ float g_h2 [(size_t)N_NODES * HID];
__device__ float g_gi [(size_t)N_NODES * GI3];
__device__ float g_gi2[(size_t)LSEQ * GI3 * NB];   // [t][gatecol][b]
__device__ int   g_deg [N_NODES];
__device__ float g_dinv[N_NODES];
__device__ int   g_off [N_NODES + 1];
__device__ int   g_cursor[N_NODES];
__device__ int   g_csrc[EDGES];
__device__ float g_ccoef[EDGES];
__device__ float g_hbuf[2][NB * HID];
__device__ float g_hsum[NB * HID];
__device__ int   g_bar;

// ---------------- degree / CSR build ----------------
__global__ void k_count(const int* __restrict__ dst, int* __restrict__ deg, int E) {
    int i = blockIdx.x * 256 + threadIdx.x;
    if (i < E) atomicAdd(&deg[dst[i]], 1);
}

__global__ void k_dinv(const int* __restrict__ deg, float* __restrict__ dinv) {
    int i = blockIdx.x * 256 + threadIdx.x;
    if (i < N_NODES) dinv[i] = rsqrtf((float)(deg[i] + 1));  // +1 self loop
}

__global__ void __launch_bounds__(1024) k_scan(const int* __restrict__ deg,
                                               int* __restrict__ off,
                                               int* __restrict__ cursor) {
    __shared__ int ssum[1024];
    int tid = threadIdx.x;
    int base = tid * 32;
    int loc[32];
    int s = 0;
#pragma unroll
    for (int i = 0; i < 32; i++) { loc[i] = s; s += deg[base + i]; }
    ssum[tid] = s;
    __syncthreads();
    for (int ofs = 1; ofs < 1024; ofs <<= 1) {
        int v = (tid >= ofs) ? ssum[tid - ofs] : 0;
        __syncthreads();
        ssum[tid] += v;
        __syncthreads();
    }
    int pre = (tid == 0) ? 0 : ssum[tid - 1];
#pragma unroll
    for (int i = 0; i < 32; i++) { off[base + i] = pre + loc[i]; cursor[base + i] = 0; }
    if (tid == 1023) off[N_NODES] = ssum[1023];
}

__global__ void k_fill(const int* __restrict__ src, const int* __restrict__ dst,
                       const float* __restrict__ dinv, const int* __restrict__ off,
                       int* __restrict__ cursor, int* __restrict__ csrc,
                       float* __restrict__ ccoef, int E) {
    int e = blockIdx.x * 256 + threadIdx.x;
    if (e >= E) return;
    int s = src[e], d = dst[e];
    int p = atomicAdd(&cursor[d], 1);
    int slot = off[d] + p;
    csrc[slot] = s;
    ccoef[slot] = dinv[s] * dinv[d];
}

__global__ void k_embed(const int* __restrict__ x, const float* __restrict__ emb,
                        float* __restrict__ h0) {
    int n = blockIdx.x;
    int d = threadIdx.x;          // 256 threads
    h0[(size_t)n * DIM + d] = emb[(size_t)x[n] * DIM + d];
}

// ---------------- CSR gather: out = relu( sum_in t[src]*coef + t[n]*dinv^2 + bias )
__global__ void __launch_bounds__(256) k_gather(
    const float* __restrict__ t, const int* __restrict__ csrc,
    const float* __restrict__ ccoef, const int* __restrict__ off,
    const float* __restrict__ dinv, const float* __restrict__ bias,
    float* __restrict__ out) {
    int w = threadIdx.x >> 5, lane = threadIdx.x & 31;
    int n = blockIdx.x * 2 + (w >> 2);
    int chunk = w & 3;
    int c4 = chunk * 32 + lane;   // float4 column index 0..127
    float di = dinv[n];
    float sc = di * di;
    float4 v = ((const float4*)(t + (size_t)n * HID))[c4];
    float4 acc = {v.x * sc, v.y * sc, v.z * sc, v.w * sc};
    int j0 = off[n], j1 = off[n + 1];
#pragma unroll 2
    for (int j = j0; j < j1; j++) {
        int s = __ldg(&csrc[j]);
        float cf = __ldg(&ccoef[j]);
        float4 u = ((const float4*)(t + (size_t)s * HID))[c4];
        acc.x += u.x * cf; acc.y += u.y * cf; acc.z += u.z * cf; acc.w += u.w * cf;
    }
    float4 bb = ((const float4*)bias)[c4];
    float4 o = {fmaxf(acc.x + bb.x, 0.f), fmaxf(acc.y + bb.y, 0.f),
                fmaxf(acc.z + bb.z, 0.f), fmaxf(acc.w + bb.w, 0.f)};
    ((float4*)(out + (size_t)n * HID))[c4] = o;
}

// ---------------- tiled SGEMM: C[M,N] = A[M,K] @ (B or B^T) (+bias) ----------------
template<bool TRANSB, bool ADD_BIAS>
__global__ void __launch_bounds__(256) sgemm_kernel(
    const float* __restrict__ A, const float* __restrict__ B,
    const float* __restrict__ bias, float* __restrict__ C,
    int M, int N, int K) {
    __shared__ float As[16][64];
    __shared__ float Bs[16][64];
    int tid = threadIdx.x;
    int tx = tid & 15, ty = tid >> 4;
    int row0 = blockIdx.y * 64;
    int col0 = blockIdx.x * 64;
    float acc[4][4] = {};
    int la_m = tid >> 2;
    int la_k = (tid & 3) << 2;
    for (int kk = 0; kk < K; kk += 16) {
        {
            float4 v = *(const float4*)(A + (size_t)(row0 + la_m) * K + kk + la_k);
            As[la_k + 0][la_m] = v.x; As[la_k + 1][la_m] = v.y;
            As[la_k + 2][la_m] = v.z; As[la_k + 3][la_m] = v.w;
        }
        if (TRANSB) {
            float4 v = *(const float4*)(B + (size_t)(col0 + la_m) * K + kk + la_k);
            Bs[la_k + 0][la_m] = v.x; Bs[la_k + 1][la_m] = v.y;
            Bs[la_k + 2][la_m] = v.z; Bs[la_k + 3][la_m] = v.w;
        } else {
            int lb_k = tid >> 4;
            int lb_n = (tid & 15) << 2;
            float4 v = *(const float4*)(B + (size_t)(kk + lb_k) * N + col0 + lb_n);
            *(float4*)&Bs[lb_k][lb_n] = v;
        }
        __syncthreads();
#pragma unroll
        for (int k = 0; k < 16; k++) {
            float4 a  = *(const float4*)&As[k][ty << 2];
            float4 bv = *(const float4*)&Bs[k][tx << 2];
            acc[0][0] += a.x * bv.x; acc[0][1] += a.x * bv.y; acc[0][2] += a.x * bv.z; acc[0][3] += a.x * bv.w;
            acc[1][0] += a.y * bv.x; acc[1][1] += a.y * bv.y; acc[1][2] += a.y * bv.z; acc[1][3] += a.y * bv.w;
            acc[2][0] += a.z * bv.x; acc[2][1] += a.z * bv.y; acc[2][2] += a.z * bv.z; acc[2][3] += a.z * bv.w;
            acc[3][0] += a.w * bv.x; acc[3][1] += a.w * bv.y; acc[3][2] += a.w * bv.z; acc[3][3] += a.w * bv.w;
        }
        __syncthreads();
    }
    float4 bb = {0, 0, 0, 0};
    if (ADD_BIAS) bb = *(const float4*)(bias + col0 + (tx << 2));
#pragma unroll
    for (int i = 0; i < 4; i++) {
        float4 o = {acc[i][0] + bb.x, acc[i][1] + bb.y, acc[i][2] + bb.z, acc[i][3] + bb.w};
        *(float4*)(C + (size_t)(row0 + (ty << 2) + i) * N + col0 + (tx << 2)) = o;
    }
}

// ---------------- gi transpose: gi[b*512+t][j] -> gi2[t][j][b] ----------------
__global__ void __launch_bounds__(256) k_tr(const float* __restrict__ gi,
                                            float* __restrict__ gi2) {
    __shared__ float s[64][132];
    int tid = threadIdx.x;
    int t = blockIdx.x;
    int j0 = blockIdx.y * 128;
#pragma unroll
    for (int i = 0; i < 8; i++) {
        int idx = tid + i * 256;
        int b = idx >> 5, c4 = idx & 31;
        float4 v = ((const float4*)(gi + (size_t)(b * LSEQ + t) * GI3 + j0))[c4];
        *(float4*)&s[b][c4 * 4] = v;
    }
    __syncthreads();
    size_t obase = (size_t)t * (GI3 * NB);
#pragma unroll
    for (int i = 0; i < 32; i++) {
        int idx = tid + i * 256;
        int j = idx >> 6, b = idx & 63;
        gi2[obase + (size_t)(j0 + j) * NB + b] = s[b][j];
    }
}

// ---------------- persistent GRU ----------------
// Round-2 structure (known good): 128 blocks x 256 threads, block per 4 cols,
// 8-way split-K, smem reduction. ONLY change: inner dots use fma.rn.f32x2 on
// (x,y)/(z,w) pairs, halving FFMA-pipe issue; horizontal add deferred to the
// reduction write.
#define HS_F4   8192
#define WS_F4   (12 * 130)
#define RED_F   (256 * 26)
#define GRU_SMEM ((HS_F4 + WS_F4) * 16 + RED_F * 4)

__device__ __forceinline__ float sigmoidf_(float x) { return 1.0f / (1.0f + __expf(-x)); }

__global__ void __launch_bounds__(256, 1) k_gru_all(
    const float* __restrict__ gi2, const float* __restrict__ Whh,
    const float* __restrict__ bhh, float* __restrict__ hsum,
    float* __restrict__ hbuf0, float* __restrict__ hbuf1, int* bar) {
    extern __shared__ float sm[];
    float4* hs4 = (float4*)sm;
    float4* ws4 = hs4 + HS_F4;
    float*  red = sm + (HS_F4 + WS_F4) * 4;
    int tid = threadIdx.x;
    int bk = blockIdx.x;
    int col0 = bk * 4;

    // load Whh slice once: rows (gate*HID + col0 + c) for gate 0..2, c 0..3
#pragma unroll
    for (int i = 0; i < 6; i++) {
        int idx = tid + i * 256;
        int r = idx >> 7, k4 = idx & 127;
        int wrow = (r >> 2) * HID + col0 + (r & 3);
        ws4[r * 130 + k4] = __ldg((const float4*)Whh + (size_t)wrow * 128 + k4);
    }

    // gate-phase identity
    int gb = tid >> 2, gc = tid & 3;
    int col = col0 + gc;
    float bh_r = bhh[col], bh_z = bhh[HID + col], bh_n = bhh[2 * HID + col];
    int wkp = ((gc >> 1) << 4) + (gb >> 2);
    int iip = ((gc & 1) << 2) + (gb & 3);
    int hxor = bk ^ ((gb >> 2) & 7);
    float hsum_acc = 0.0f;

    // worker identity: 4 graphs x 2 cols x 3 gates, 8 k-groups
    int wk = tid & 31, kg = tid >> 5;
    int c2 = wk >> 4, bq = wk & 15;
    int xorb = bq & 7;
    int b0 = bq * 4;
    int kbase = kg * 16;
    const float4* hp0 = hs4 + (size_t)(b0 + 0) * 128;
    const float4* hp1 = hs4 + (size_t)(b0 + 1) * 128;
    const float4* hp2 = hs4 + (size_t)(b0 + 2) * 128;
    const float4* hp3 = hs4 + (size_t)(b0 + 3) * 128;
    const float4* wp0 = ws4 + (0 * 4 + c2 * 2) * 130;   // gate r, cols cc=0,1
    const float4* wp1 = ws4 + (1 * 4 + c2 * 2) * 130;   // gate z
    const float4* wp2 = ws4 + (2 * 4 + c2 * 2) * 130;   // gate n

    __syncthreads();

    for (int t = 0; t < LSEQ; t++) {
        const float* hb = (t & 1) ? hbuf1 : hbuf0;
        float*       hn = (t & 1) ? hbuf0 : hbuf1;

        // prefetch gate inputs for this step (hidden under staging+compute)
        size_t gbase = (size_t)t * (GI3 * NB) + (size_t)col * NB + gb;
        float gir = __ldcg(gi2 + gbase);
        float giz = __ldcg(gi2 + gbase + (size_t)HID * NB);
        float gin = __ldcg(gi2 + gbase + (size_t)(2 * HID) * NB);

        // stage h (bypass L1 - other SMs wrote it)
#pragma unroll
        for (int i = 0; i < 32; i++) {
            int idx = tid + i * 256;
            int b = idx >> 7, k4 = idx & 127;
            float4 v = __ldcg((const float4*)hb + idx);
            hs4[b * 128 + (k4 ^ ((b >> 2) & 7))] = v;
        }
        __syncthreads();

        // partial dots over this k-group (pairwise f32x2: lane0=k-even, lane1=k-odd)
        unsigned long long acc[3][2][4];
#pragma unroll
        for (int g = 0; g < 3; g++)
#pragma unroll
            for (int cc = 0; cc < 2; cc++)
#pragma unroll
                for (int i = 0; i < 4; i++) acc[g][cc][i] = 0ull;
#pragma unroll
        for (int kk = 0; kk < 16; kk++) {
            int k4 = kbase + kk;
            int hk = k4 ^ xorb;
            ulonglong2 h0 = *(const ulonglong2*)(hp0 + hk);
            ulonglong2 h1 = *(const ulonglong2*)(hp1 + hk);
            ulonglong2 h2 = *(const ulonglong2*)(hp2 + hk);
            ulonglong2 h3 = *(const ulonglong2*)(hp3 + hk);
#pragma unroll
            for (int cc = 0; cc < 2; cc++) {
                ulonglong2 wr = *(const ulonglong2*)(wp0 + cc * 130 + k4);
                ulonglong2 wz = *(const ulonglong2*)(wp1 + cc * 130 + k4);
                ulonglong2 wn = *(const ulonglong2*)(wp2 + cc * 130 + k4);
                FMA2(acc[0][cc][0], h0.x, wr.x, acc[0][cc][0]); FMA2(acc[0][cc][0], h0.y, wr.y, acc[0][cc][0]);
                FMA2(acc[0][cc][1], h1.x, wr.x, acc[0][cc][1]); FMA2(acc[0][cc][1], h1.y, wr.y, acc[0][cc][1]);
                FMA2(acc[0][cc][2], h2.x, wr.x, acc[0][cc][2]); FMA2(acc[0][cc][2], h2.y, wr.y, acc[0][cc][2]);
                FMA2(acc[0][cc][3], h3.x, wr.x, acc[0][cc][3]); FMA2(acc[0][cc][3], h3.y, wr.y, acc[0][cc][3]);
                FMA2(acc[1][cc][0], h0.x, wz.x, acc[1][cc][0]); FMA2(acc[1][cc][0], h0.y, wz.y, acc[1][cc][0]);
                FMA2(acc[1][cc][1], h1.x, wz.x, acc[1][cc][1]); FMA2(acc[1][cc][1], h1.y, wz.y, acc[1][cc][1]);
                FMA2(acc[1][cc][2], h2.x, wz.x, acc[1][cc][2]); FMA2(acc[1][cc][2], h2.y, wz.y, acc[1][cc][2]);
                FMA2(acc[1][cc][3], h3.x, wz.x, acc[1][cc][3]); FMA2(acc[1][cc][3], h3.y, wz.y, acc[1][cc][3]);
                FMA2(acc[2][cc][0], h0.x, wn.x, acc[2][cc][0]); FMA2(acc[2][cc][0], h0.y, wn.y, acc[2][cc][0]);
                FMA2(acc[2][cc][1], h1.x, wn.x, acc[2][cc][1]); FMA2(acc[2][cc][1], h1.y, wn.y, acc[2][cc][1]);
                FMA2(acc[2][cc][2], h2.x, wn.x, acc[2][cc][2]); FMA2(acc[2][cc][2], h2.y, wn.y, acc[2][cc][2]);
                FMA2(acc[2][cc][3], h3.x, wn.x, acc[2][cc][3]); FMA2(acc[2][cc][3], h3.y, wn.y, acc[2][cc][3]);
            }
        }
        {
            float* rp = red + (kg * 32 + wk) * 26;
#pragma unroll
            for (int g = 0; g < 3; g++)
#pragma unroll
                for (int cc = 0; cc < 2; cc++)
#pragma unroll
                    for (int i = 0; i < 4; i++) {
                        float2 f = *(float2*)&acc[g][cc][i];
                        rp[g * 8 + cc * 4 + i] = f.x + f.y;
                    }
        }
        __syncthreads();

        // reduce across 8 k-groups + gates + state update
        float s0 = 0, s1 = 0, s2 = 0;
#pragma unroll
        for (int q = 0; q < 8; q++) {
            const float* rp = red + (q * 32 + wkp) * 26 + iip;
            s0 += rp[0]; s1 += rp[8]; s2 += rp[16];
        }
        float r  = sigmoidf_(gir + s0 + bh_r);
        float z  = sigmoidf_(giz + s1 + bh_z);
        float nn = tanhf(gin + r * (s2 + bh_n));
        float hold = ((const float*)(hs4 + (size_t)gb * 128 + hxor))[gc];
        float hnew = (1.0f - z) * nn + z * hold;
        __stcg(hn + gb * HID + col, hnew);
        hsum_acc += hnew;

        // chip-wide barrier
        __threadfence();
        __syncthreads();
        if (tid == 0) {
            atomicAdd(bar, 1);
            int target = NBLK_GRU * (t + 1);
            while (*((volatile int*)bar) < target) { }
        }
        __syncthreads();
    }
    hsum[gb * HID + col] = hsum_acc;
}

// ---------------- head ----------------
__global__ void __launch_bounds__(512) k_head(
    const float* __restrict__ hsum, const float* __restrict__ focal,
    const float* __restrict__ fc1w, const float* __restrict__ fc1b,
    const float* __restrict__ fc2w, const float* __restrict__ fc2b,
    float* __restrict__ out) {
    __shared__ float g[HID + 1];
    __shared__ float red[HID];
    int b = blockIdx.x, j = threadIdx.x;
    g[j] = hsum[b * HID + j] * (1.0f / (float)LSEQ);
    if (j == 0) g[HID] = focal[b];
    __syncthreads();
    float acc = fc1b[j];
    for (int k = 0; k < HID + 1; k++) acc += g[k] * fc1w[(size_t)k * HID + j];
    float a = fmaxf(acc, 0.0f);
    red[j] = a * fc2w[j];
    __syncthreads();
    for (int s = 256; s > 0; s >>= 1) {
        if (j < s) red[j] += red[j + s];
        __syncthreads();
    }
    if (j == 0) out[b] = sigmoidf_(red[0] + fc2b[0]);
}

// ---------------- launch ----------------
extern "C" void kernel_launch(void* const* d_in, const int* in_sizes, int n_in,
                              void* d_out, int out_size) {
    const int*   x     = (const int*)  d_in[0];
    const int*   edge  = (const int*)  d_in[1];
    const float* focal = (const float*)d_in[3];
    const float* emb   = (const float*)d_in[4];
    const float* W1    = (const float*)d_in[5];
    const float* b1    = (const float*)d_in[6];
    const float* W2    = (const float*)d_in[7];
    const float* b2    = (const float*)d_in[8];
    const float* Wih   = (const float*)d_in[9];
    const float* Whh   = (const float*)d_in[10];
    const float* bih   = (const float*)d_in[11];
    const float* bhh   = (const float*)d_in[12];
    const float* fc1w  = (const float*)d_in[13];
    const float* fc1b  = (const float*)d_in[14];
    const float* fc2w  = (const float*)d_in[15];
    const float* fc2b  = (const float*)d_in[16];
    int E = in_sizes[1] / 2;
    const int* src = edge;
    const int* dst = edge + E;

    float *h0, *t, *h1, *h2, *gi, *gi2, *dinv, *hbuf, *hsum, *ccoef;
    int *deg, *off, *cursor, *csrc, *bar;
    cudaGetSymbolAddress((void**)&h0,    g_h0);
    cudaGetSymbolAddress((void**)&t,     g_t);
    cudaGetSymbolAddress((void**)&h1,    g_h1);
    cudaGetSymbolAddress((void**)&h2,    g_h2);
    cudaGetSymbolAddress((void**)&gi,    g_gi);
    cudaGetSymbolAddress((void**)&gi2,   g_gi2);
    cudaGetSymbolAddress((void**)&deg,   g_deg);
    cudaGetSymbolAddress((void**)&dinv,  g_dinv);
    cudaGetSymbolAddress((void**)&off,   g_off);
    cudaGetSymbolAddress((void**)&cursor,g_cursor);
    cudaGetSymbolAddress((void**)&csrc,  g_csrc);
    cudaGetSymbolAddress((void**)&ccoef, g_ccoef);
    cudaGetSymbolAddress((void**)&hbuf,  g_hbuf);
    cudaGetSymbolAddress((void**)&hsum,  g_hsum);
    cudaGetSymbolAddress((void**)&bar,   g_bar);

    cudaFuncSetAttribute(k_gru_all, cudaFuncAttributeMaxDynamicSharedMemorySize, GRU_SMEM);

    // CSR build (graph fixed for both layers)
    cudaMemsetAsync(deg, 0, N_NODES * sizeof(int), 0);
    k_count<<<(E + 255) / 256, 256>>>(dst, deg, E);
    k_dinv<<<N_NODES / 256, 256>>>(deg, dinv);
    k_scan<<<1, 1024>>>(deg, off, cursor);
    k_fill<<<(E + 255) / 256, 256>>>(src, dst, dinv, off, cursor, csrc, ccoef, E);

    // GCN layer 1
    k_embed<<<N_NODES, 256>>>(x, emb, h0);
    sgemm_kernel<false, false><<<dim3(HID / 64, N_NODES / 64), 256>>>(h0, W1, nullptr, t, N_NODES, HID, DIM);
    k_gather<<<N_NODES / 2, 256>>>(t, csrc, ccoef, off, dinv, b1, h1);

    // GCN layer 2
    sgemm_kernel<false, false><<<dim3(HID / 64, N_NODES / 64), 256>>>(h1, W2, nullptr, t, N_NODES, HID, HID);
    k_gather<<<N_NODES / 2, 256>>>(t, csrc, ccoef, off, dinv, b2, h2);

    // GRU input gates for all timesteps: gi = h2 @ Wih^T + bih, then transpose
    sgemm_kernel<true, true><<<dim3(GI3 / 64, N_NODES / 64), 256>>>(h2, Wih, bih, gi, N_NODES, GI3, HID);
    k_tr<<<dim3(LSEQ, GI3 / 128), 256>>>(gi, gi2);

    // persistent GRU
    cudaMemsetAsync(hbuf, 0, NB * HID * sizeof(float), 0);   // hbuf[0] = h_0 = 0
    cudaMemsetAsync(bar, 0, sizeof(int), 0);
    k_gru_all<<<NBLK_GRU, 256, GRU_SMEM>>>(gi2, Whh, bhh, hsum, hbuf, hbuf + NB * HID, bar);

    // head
    k_head<<<NB, 512>>>(hsum, focal, fc1w, fc1b, fc2w, fc2b, (float*)d_out);
}